// round 1
// baseline (speedup 1.0000x reference)
#include <cuda_runtime.h>
#include <cstdint>

#define E_N    200000
#define P_N    50000
#define D_N    128
#define NNZ_N  2000000
#define C_N    32
#define NSEED_N 320

// ---------------- scratch (device globals; no allocation allowed) ------------
__device__ float g_es [(size_t)E_N * D_N];          // es after layer 0
__device__ float g_ps [(size_t)P_N * D_N];          // ps after layer 0
__device__ float g_msg[(size_t)E_N * D_N];          // shared msg buffer (E >= P)
__device__ float g_g1 [(size_t)E_N * 3 * D_N];      // X @ Wih^T + bih
__device__ float g_g2 [(size_t)E_N * 3 * D_N];      // H @ Whh^T + bhh
__device__ __align__(16) float g_seedmean[D_N];

// ---------------- helpers ----------------------------------------------------
__device__ __forceinline__ float sigm_(float x) { return 1.0f / (1.0f + __expf(-x)); }

// ---------------- seed mean --------------------------------------------------
__global__ void seedmean_kernel(const int* __restrict__ sidx,
                                const float* __restrict__ es) {
    __shared__ int s[NSEED_N];
    for (int i = threadIdx.x; i < NSEED_N; i += 128) s[i] = sidx[i];
    __syncthreads();
    float acc = 0.0f;
    #pragma unroll 8
    for (int i = 0; i < NSEED_N; i++)
        acc += __ldg(es + (size_t)s[i] * D_N + threadIdx.x);
    g_seedmean[threadIdx.x] = acc * (1.0f / NSEED_N);
}

// ---------------- fills ------------------------------------------------------
__global__ void zero_kernel(float* __restrict__ p, int n4) {
    int i = blockIdx.x * blockDim.x + threadIdx.x;
    if (i < n4) ((float4*)p)[i] = make_float4(0.f, 0.f, 0.f, 0.f);
}

__global__ void bcast_mean_kernel(float* __restrict__ p, int n4) {
    int i = blockIdx.x * blockDim.x + threadIdx.x;
    if (i < n4) ((float4*)p)[i] = ((const float4*)g_seedmean)[i & 31];
}

// ---------------- edge scatter: dst[dcol] += table[srow] * w -----------------
__global__ void scatter_kernel(const float* __restrict__ table,
                               const int*   __restrict__ src_idx,
                               const int*   __restrict__ dst_idx,
                               const float* __restrict__ vals,
                               float*       __restrict__ dst) {
    int g = blockIdx.x * blockDim.x + threadIdx.x;
    int e = g >> 5;
    if (e >= NNZ_N) return;
    int lane = g & 31;
    int s  = __ldg(src_idx + e);
    int d  = __ldg(dst_idx + e);
    float w = __ldg(vals + e);
    float4 v = *(const float4*)(table + (size_t)s * D_N + lane * 4);
    float* o = dst + (size_t)d * D_N + lane * 4;
    atomicAdd(o + 0, v.x * w);
    atomicAdd(o + 1, v.y * w);
    atomicAdd(o + 2, v.z * w);
    atomicAdd(o + 3, v.w * w);
}

// ---------------- GEMM: C[M,384] = A[M,128] @ W[384,128]^T + bias ------------
#define BM 128
#define BN 64
#define BK 128
#define GEMM_SMEM ((BK * BM + BK * BN) * 4)

__global__ __launch_bounds__(128, 2)
void gemm_kernel(const float* __restrict__ A, const float* __restrict__ W,
                 const float* __restrict__ bias, float* __restrict__ Cmat, int M) {
    extern __shared__ float smem[];
    float* As = smem;               // [BK][BM] k-major
    float* Ws = smem + BK * BM;     // [BK][BN] k-major

    const int tid  = threadIdx.x;
    const int row0 = blockIdx.y * BM;
    const int col0 = blockIdx.x * BN;

    // Load A tile (transposed into k-major). Lanes cover consecutive rows:
    // shared stores conflict-free; global reads are 16B strided (L2-resident).
    #pragma unroll
    for (int it = 0; it < 32; it++) {
        int idx = it * 128 + tid;
        int row = idx & 127;
        int kq  = idx >> 7;
        float4 v = make_float4(0.f, 0.f, 0.f, 0.f);
        int grow = row0 + row;
        if (grow < M) v = *(const float4*)(A + (size_t)grow * 128 + kq * 4);
        As[(kq * 4 + 0) * BM + row] = v.x;
        As[(kq * 4 + 1) * BM + row] = v.y;
        As[(kq * 4 + 2) * BM + row] = v.z;
        As[(kq * 4 + 3) * BM + row] = v.w;
    }
    #pragma unroll
    for (int it = 0; it < 16; it++) {
        int idx = it * 128 + tid;
        int col = idx & 63;
        int kq  = idx >> 6;
        float4 v = *(const float4*)(W + (size_t)(col0 + col) * 128 + kq * 4);
        Ws[(kq * 4 + 0) * BN + col] = v.x;
        Ws[(kq * 4 + 1) * BN + col] = v.y;
        Ws[(kq * 4 + 2) * BN + col] = v.z;
        Ws[(kq * 4 + 3) * BN + col] = v.w;
    }
    __syncthreads();

    const int tx = tid & 7;    // 8 col groups
    const int ty = tid >> 3;   // 16 row groups
    float acc[8][8];
    #pragma unroll
    for (int i = 0; i < 8; i++)
        #pragma unroll
        for (int j = 0; j < 8; j++) acc[i][j] = 0.f;

    #pragma unroll 8
    for (int k = 0; k < BK; k++) {
        float4 a0 = *(const float4*)&As[k * BM + ty * 8];
        float4 a1 = *(const float4*)&As[k * BM + ty * 8 + 4];
        float4 b0 = *(const float4*)&Ws[k * BN + tx * 8];
        float4 b1 = *(const float4*)&Ws[k * BN + tx * 8 + 4];
        float av[8] = {a0.x, a0.y, a0.z, a0.w, a1.x, a1.y, a1.z, a1.w};
        float bv[8] = {b0.x, b0.y, b0.z, b0.w, b1.x, b1.y, b1.z, b1.w};
        #pragma unroll
        for (int i = 0; i < 8; i++)
            #pragma unroll
            for (int j = 0; j < 8; j++)
                acc[i][j] += av[i] * bv[j];
    }

    float bj[8];
    #pragma unroll
    for (int j = 0; j < 8; j++) bj[j] = __ldg(bias + col0 + tx * 8 + j);

    #pragma unroll
    for (int i = 0; i < 8; i++) {
        int grow = row0 + ty * 8 + i;
        if (grow >= M) continue;
        float* crow = Cmat + (size_t)grow * 384 + col0 + tx * 8;
        float4 o0 = make_float4(acc[i][0] + bj[0], acc[i][1] + bj[1],
                                acc[i][2] + bj[2], acc[i][3] + bj[3]);
        float4 o1 = make_float4(acc[i][4] + bj[4], acc[i][5] + bj[5],
                                acc[i][6] + bj[6], acc[i][7] + bj[7]);
        *(float4*)(crow)     = o0;
        *(float4*)(crow + 4) = o1;
    }
}

// ---------------- GRU gates --------------------------------------------------
__global__ void gate_kernel(const float* __restrict__ g1, const float* __restrict__ g2,
                            const float* __restrict__ hin, float* __restrict__ hout, int M) {
    int idx = blockIdx.x * blockDim.x + threadIdx.x;   // over M*32 float4s
    if (idx >= M * 32) return;
    int m = idx >> 5;
    int q = idx & 31;
    const float4* G1 = (const float4*)(g1 + (size_t)m * 384);
    const float4* G2 = (const float4*)(g2 + (size_t)m * 384);
    float4 xr = G1[q],      hr = G2[q];
    float4 xz = G1[32 + q], hz = G2[32 + q];
    float4 xn = G1[64 + q], hn = G2[64 + q];
    float4 h  = ((const float4*)hin)[idx];
    float4 o;
    {
        float r = sigm_(xr.x + hr.x), z = sigm_(xz.x + hz.x);
        float n = tanhf(xn.x + r * hn.x);
        o.x = (1.f - z) * n + z * h.x;
    }
    {
        float r = sigm_(xr.y + hr.y), z = sigm_(xz.y + hz.y);
        float n = tanhf(xn.y + r * hn.y);
        o.y = (1.f - z) * n + z * h.y;
    }
    {
        float r = sigm_(xr.z + hr.z), z = sigm_(xz.z + hz.z);
        float n = tanhf(xn.z + r * hn.z);
        o.z = (1.f - z) * n + z * h.z;
    }
    {
        float r = sigm_(xr.w + hr.w), z = sigm_(xz.w + hz.w);
        float n = tanhf(xn.w + r * hn.w);
        o.w = (1.f - z) * n + z * h.w;
    }
    ((float4*)hout)[idx] = o;
}

// ---------------- classifier head: out[E,32] = es @ fc_w^T + fc_b ------------
__global__ void logits_kernel(const float* __restrict__ es, const float* __restrict__ fw,
                              const float* __restrict__ fb, float* __restrict__ out) {
    __shared__ float ws[32][129];   // pad -> conflict-free (c+k)%32
    __shared__ float wb[32];
    int tid = threadIdx.x;          // 256
    for (int i = tid; i < 32 * 128; i += 256) {
        int c = i >> 7, k = i & 127;
        ws[c][k] = fw[c * 128 + k];
    }
    if (tid < 32) wb[tid] = fb[tid];
    __syncthreads();
    int c  = tid & 31;
    int rl = tid >> 5;
    int row = blockIdx.x * 8 + rl;
    if (row >= E_N) return;
    const float* er = es + (size_t)row * 128;
    float acc = 0.f;
    #pragma unroll
    for (int k = 0; k < 128; k++) acc += er[k] * ws[c][k];  // er[k] warp-broadcast
    out[(size_t)row * 32 + c] = acc + wb[c];
}

// ---------------- host orchestration -----------------------------------------
extern "C" void kernel_launch(void* const* d_in, const int* in_sizes, int n_in,
                              void* d_out, int out_size) {
    const int*   seed_index = (const int*)  d_in[0];
    const float* es_in      = (const float*)d_in[1];
    const float* ps_in      = (const float*)d_in[2];
    const int*   erows      = (const int*)  d_in[3];
    const int*   ecols      = (const int*)  d_in[4];
    const float* evals      = (const float*)d_in[5];
    const float* prm[16];
    for (int i = 0; i < 16; i++) prm[i] = (const float*)d_in[6 + i];
    const float* fc_w = (const float*)d_in[22];
    const float* fc_b = (const float*)d_in[23];

    float* out        = (float*)d_out;
    float* out_logits = out;
    float* out_es     = out + (size_t)E_N * C_N;
    float* out_ps     = out_es + (size_t)E_N * D_N;

    float *p_es, *p_ps, *p_msg, *p_g1, *p_g2;
    cudaGetSymbolAddress((void**)&p_es,  g_es);
    cudaGetSymbolAddress((void**)&p_ps,  g_ps);
    cudaGetSymbolAddress((void**)&p_msg, g_msg);
    cudaGetSymbolAddress((void**)&p_g1,  g_g1);
    cudaGetSymbolAddress((void**)&p_g2,  g_g2);

    cudaFuncSetAttribute(gemm_kernel,
                         cudaFuncAttributeMaxDynamicSharedMemorySize, GEMM_SMEM);

    const int scat_blocks = (NNZ_N * 32 + 255) / 256;
    const int p_rows = (P_N + BM - 1) / BM;
    const int e_rows = (E_N + BM - 1) / BM;

    for (int l = 0; l < 2; l++) {
        const float* eW[4] = {prm[l*8+0], prm[l*8+1], prm[l*8+2], prm[l*8+3]};
        const float* pW[4] = {prm[l*8+4], prm[l*8+5], prm[l*8+6], prm[l*8+7]};
        const float* es_src = (l == 0) ? es_in : p_es;
        const float* ps_src = (l == 0) ? ps_in : p_ps;
        float* es_dst = (l == 0) ? p_es : out_es;
        float* ps_dst = (l == 0) ? p_ps : out_ps;

        // seed mean of es at layer start
        seedmean_kernel<<<1, 128>>>(seed_index, es_src);

        // p_msg = segment_sum(es[edge_rows] * w, edge_cols)
        {
            int n4 = P_N * 32;
            zero_kernel<<<(n4 + 255) / 256, 256>>>(p_msg, n4);
        }
        scatter_kernel<<<scat_blocks, 256>>>(es_src, erows, ecols, evals, p_msg);

        // ps = GRU(p_msg, ps)
        gemm_kernel<<<dim3(6, p_rows), 128, GEMM_SMEM>>>(p_msg,  pW[0], pW[2], p_g1, P_N);
        gemm_kernel<<<dim3(6, p_rows), 128, GEMM_SMEM>>>(ps_src, pW[1], pW[3], p_g2, P_N);
        gate_kernel<<<(P_N * 32 + 255) / 256, 256>>>(p_g1, p_g2, ps_src, ps_dst, P_N);

        // e_msg = seed_mean + segment_sum(ps_new[edge_cols] * w, edge_rows)
        {
            int n4 = E_N * 32;
            bcast_mean_kernel<<<(n4 + 255) / 256, 256>>>(p_msg, n4);
        }
        scatter_kernel<<<scat_blocks, 256>>>(ps_dst, ecols, erows, evals, p_msg);

        // es = GRU(e_msg, es)
        gemm_kernel<<<dim3(6, e_rows), 128, GEMM_SMEM>>>(p_msg,  eW[0], eW[2], p_g1, E_N);
        gemm_kernel<<<dim3(6, e_rows), 128, GEMM_SMEM>>>(es_src, eW[1], eW[3], p_g2, E_N);
        gate_kernel<<<(E_N * 32 + 255) / 256, 256>>>(p_g1, p_g2, es_src, es_dst, E_N);
    }

    // logits = es @ fc_w^T + fc_b
    logits_kernel<<<(E_N + 7) / 8, 256>>>(out_es, fc_w, fc_b, out_logits);

    (void)in_sizes; (void)n_in; (void)out_size;
}

// round 13
// speedup vs baseline: 1.6503x; 1.6503x over previous
#include <cuda_runtime.h>
#include <cstdint>

#define E_N    200000
#define P_N    50000
#define D_N    128
#define NNZ_N  2000000
#define C_N    32
#define NSEED_N 320

// ---------------- scratch (device globals; no allocation allowed) ------------
__device__ float g_es [(size_t)E_N * D_N];
__device__ float g_ps [(size_t)P_N * D_N];
__device__ float g_msg[(size_t)E_N * D_N];
__device__ float g_g1 [(size_t)E_N * 3 * D_N];
__device__ float g_g2 [(size_t)E_N * 3 * D_N];
__device__ __align__(16) float g_seedmean[D_N];

// ---------------- helpers ----------------------------------------------------
__device__ __forceinline__ float sigm_(float x) { return 1.0f / (1.0f + __expf(-x)); }

__device__ __forceinline__ uint32_t f2tf32(float f) {
    uint32_t u;
    asm("cvt.rna.tf32.f32 %0, %1;" : "=r"(u) : "f"(f));
    return u;
}

// ---------------- seed mean --------------------------------------------------
__global__ void seedmean_kernel(const int* __restrict__ sidx,
                                const float* __restrict__ es) {
    __shared__ int s[NSEED_N];
    for (int i = threadIdx.x; i < NSEED_N; i += 128) s[i] = sidx[i];
    __syncthreads();
    float acc = 0.0f;
    #pragma unroll 8
    for (int i = 0; i < NSEED_N; i++)
        acc += __ldg(es + (size_t)s[i] * D_N + threadIdx.x);
    g_seedmean[threadIdx.x] = acc * (1.0f / NSEED_N);
}

// ---------------- fills ------------------------------------------------------
__global__ void zero_kernel(float* __restrict__ p, int n4) {
    int i = blockIdx.x * blockDim.x + threadIdx.x;
    if (i < n4) ((float4*)p)[i] = make_float4(0.f, 0.f, 0.f, 0.f);
}

__global__ void bcast_mean_kernel(float* __restrict__ p, int n4) {
    int i = blockIdx.x * blockDim.x + threadIdx.x;
    if (i < n4) ((float4*)p)[i] = ((const float4*)g_seedmean)[i & 31];
}

// ---------------- edge scatter: dst[dcol] += table[srow] * w -----------------
// One warp per edge; each lane owns a 16B sector of the 512B row and issues a
// single vectorized reduction (red.global.add.v4.f32, sm_90+) instead of 4
// scalar atomics -> 4x fewer LSU/L2-atomic dispatches.
__global__ void scatter_kernel(const float* __restrict__ table,
                               const int*   __restrict__ src_idx,
                               const int*   __restrict__ dst_idx,
                               const float* __restrict__ vals,
                               float*       __restrict__ dst) {
    int g = blockIdx.x * blockDim.x + threadIdx.x;
    int e = g >> 5;
    if (e >= NNZ_N) return;
    int lane = g & 31;
    int s  = __ldg(src_idx + e);
    int d  = __ldg(dst_idx + e);
    float w = __ldg(vals + e);
    float4 v = *(const float4*)(table + (size_t)s * D_N + lane * 4);
    float* o = dst + (size_t)d * D_N + lane * 4;
    asm volatile("red.global.add.v4.f32 [%0], {%1, %2, %3, %4};"
                 :: "l"(o), "f"(v.x * w), "f"(v.y * w), "f"(v.z * w), "f"(v.w * w)
                 : "memory");
}

// ---------------- tf32 tensor-core GEMM --------------------------------------
// C[M,384] = A[M,128] @ W[384,128]^T + bias
// CTA: 256 threads, tile 128(M) x 64(N), full K=128 staged in smem.
// Smem layout k-major with row stride = extent + 8 words -> conflict-free
// fragment loads (bank = 8*tg + gid + const).
#define TBM 128
#define TBN 64
#define A_STRIDE 136   // 128 + 8
#define B_STRIDE 72    // 64 + 8
#define GEMM_SMEM ((128 * A_STRIDE + 128 * B_STRIDE) * 4)

__global__ __launch_bounds__(256, 1)
void gemm_tf32_kernel(const float* __restrict__ A, const float* __restrict__ W,
                      const float* __restrict__ bias, float* __restrict__ Cmat, int M) {
    extern __shared__ uint32_t smem[];
    uint32_t* As = smem;                    // [k=128][m stride 136]
    uint32_t* Bs = smem + 128 * A_STRIDE;   // [k=128][n stride 72]

    const int tid  = threadIdx.x;
    const int row0 = blockIdx.y * TBM;
    const int col0 = blockIdx.x * TBN;

    // Stage A tile (k-major, converted to tf32). One row per lane ->
    // conflict-free STS; global reads are 16B strided (L2-resident).
    #pragma unroll
    for (int it = 0; it < 16; it++) {
        int idx = it * 256 + tid;
        int row = idx & 127;
        int kq  = idx >> 7;                 // 0..31, float4 within the k-row
        float4 v = make_float4(0.f, 0.f, 0.f, 0.f);
        int grow = row0 + row;
        if (grow < M) v = *(const float4*)(A + (size_t)grow * 128 + kq * 4);
        As[(kq * 4 + 0) * A_STRIDE + row] = f2tf32(v.x);
        As[(kq * 4 + 1) * A_STRIDE + row] = f2tf32(v.y);
        As[(kq * 4 + 2) * A_STRIDE + row] = f2tf32(v.z);
        As[(kq * 4 + 3) * A_STRIDE + row] = f2tf32(v.w);
    }
    // Stage W tile: Bs[k][n] = W[col0+n][k]
    #pragma unroll
    for (int it = 0; it < 8; it++) {
        int idx = it * 256 + tid;
        int col = idx & 63;
        int kq  = idx >> 6;                 // 0..31
        float4 v = *(const float4*)(W + (size_t)(col0 + col) * 128 + kq * 4);
        Bs[(kq * 4 + 0) * B_STRIDE + col] = f2tf32(v.x);
        Bs[(kq * 4 + 1) * B_STRIDE + col] = f2tf32(v.y);
        Bs[(kq * 4 + 2) * B_STRIDE + col] = f2tf32(v.z);
        Bs[(kq * 4 + 3) * B_STRIDE + col] = f2tf32(v.w);
    }
    __syncthreads();

    const int lane = tid & 31;
    const int wid  = tid >> 5;              // 8 warps
    const int m0   = (wid & 3) * 32;        // 4 warp-rows of 32
    const int n0   = (wid >> 2) * 32;       // 2 warp-cols of 32
    const int gid  = lane >> 2;             // 0..7
    const int tg   = lane & 3;              // 0..3

    float acc[2][4][4];
    #pragma unroll
    for (int mi = 0; mi < 2; mi++)
        #pragma unroll
        for (int ni = 0; ni < 4; ni++)
            #pragma unroll
            for (int q = 0; q < 4; q++) acc[mi][ni][q] = 0.f;

    #pragma unroll
    for (int ks = 0; ks < 16; ks++) {
        const int k = ks * 8;
        uint32_t a[2][4], b[4][2];
        #pragma unroll
        for (int mi = 0; mi < 2; mi++) {
            int r = m0 + mi * 16 + gid;
            a[mi][0] = As[(k + tg    ) * A_STRIDE + r    ];
            a[mi][1] = As[(k + tg    ) * A_STRIDE + r + 8];
            a[mi][2] = As[(k + tg + 4) * A_STRIDE + r    ];
            a[mi][3] = As[(k + tg + 4) * A_STRIDE + r + 8];
        }
        #pragma unroll
        for (int ni = 0; ni < 4; ni++) {
            int n = n0 + ni * 8 + gid;
            b[ni][0] = Bs[(k + tg    ) * B_STRIDE + n];
            b[ni][1] = Bs[(k + tg + 4) * B_STRIDE + n];
        }
        #pragma unroll
        for (int mi = 0; mi < 2; mi++)
            #pragma unroll
            for (int ni = 0; ni < 4; ni++) {
                asm volatile(
                    "mma.sync.aligned.m16n8k8.row.col.f32.tf32.tf32.f32 "
                    "{%0,%1,%2,%3}, {%4,%5,%6,%7}, {%8,%9}, {%0,%1,%2,%3};"
                    : "+f"(acc[mi][ni][0]), "+f"(acc[mi][ni][1]),
                      "+f"(acc[mi][ni][2]), "+f"(acc[mi][ni][3])
                    : "r"(a[mi][0]), "r"(a[mi][1]), "r"(a[mi][2]), "r"(a[mi][3]),
                      "r"(b[ni][0]), "r"(b[ni][1]));
            }
    }

    // Epilogue: c frag m16n8 -> (row=gid(+8), col=tg*2+{0,1})
    #pragma unroll
    for (int ni = 0; ni < 4; ni++) {
        int gcol = col0 + n0 + ni * 8 + tg * 2;
        float b0 = __ldg(bias + gcol);
        float b1 = __ldg(bias + gcol + 1);
        #pragma unroll
        for (int mi = 0; mi < 2; mi++) {
            int r = row0 + m0 + mi * 16 + gid;
            if (r < M) {
                float2 o = make_float2(acc[mi][ni][0] + b0, acc[mi][ni][1] + b1);
                *(float2*)(Cmat + (size_t)r * 384 + gcol) = o;
            }
            if (r + 8 < M) {
                float2 o = make_float2(acc[mi][ni][2] + b0, acc[mi][ni][3] + b1);
                *(float2*)(Cmat + (size_t)(r + 8) * 384 + gcol) = o;
            }
        }
    }
}

// ---------------- GRU gates --------------------------------------------------
__global__ void gate_kernel(const float* __restrict__ g1, const float* __restrict__ g2,
                            const float* __restrict__ hin, float* __restrict__ hout, int M) {
    int idx = blockIdx.x * blockDim.x + threadIdx.x;   // over M*32 float4s
    if (idx >= M * 32) return;
    int m = idx >> 5;
    int q = idx & 31;
    const float4* G1 = (const float4*)(g1 + (size_t)m * 384);
    const float4* G2 = (const float4*)(g2 + (size_t)m * 384);
    float4 xr = G1[q],      hr = G2[q];
    float4 xz = G1[32 + q], hz = G2[32 + q];
    float4 xn = G1[64 + q], hn = G2[64 + q];
    float4 h  = ((const float4*)hin)[idx];
    float4 o;
    {
        float r = sigm_(xr.x + hr.x), z = sigm_(xz.x + hz.x);
        float n = tanhf(xn.x + r * hn.x);
        o.x = (1.f - z) * n + z * h.x;
    }
    {
        float r = sigm_(xr.y + hr.y), z = sigm_(xz.y + hz.y);
        float n = tanhf(xn.y + r * hn.y);
        o.y = (1.f - z) * n + z * h.y;
    }
    {
        float r = sigm_(xr.z + hr.z), z = sigm_(xz.z + hz.z);
        float n = tanhf(xn.z + r * hn.z);
        o.z = (1.f - z) * n + z * h.z;
    }
    {
        float r = sigm_(xr.w + hr.w), z = sigm_(xz.w + hz.w);
        float n = tanhf(xn.w + r * hn.w);
        o.w = (1.f - z) * n + z * h.w;
    }
    ((float4*)hout)[idx] = o;
}

// ---------------- classifier head: out[E,32] = es @ fc_w^T + fc_b ------------
__global__ void logits_kernel(const float* __restrict__ es, const float* __restrict__ fw,
                              const float* __restrict__ fb, float* __restrict__ out) {
    __shared__ float ws[32][129];
    __shared__ float wb[32];
    int tid = threadIdx.x;          // 256
    for (int i = tid; i < 32 * 128; i += 256) {
        int c = i >> 7, k = i & 127;
        ws[c][k] = fw[c * 128 + k];
    }
    if (tid < 32) wb[tid] = fb[tid];
    __syncthreads();
    int c  = tid & 31;
    int rl = tid >> 5;
    int row = blockIdx.x * 8 + rl;
    if (row >= E_N) return;
    const float* er = es + (size_t)row * 128;
    float acc = 0.f;
    #pragma unroll
    for (int k = 0; k < 128; k++) acc += er[k] * ws[c][k];
    out[(size_t)row * 32 + c] = acc + wb[c];
}

// ---------------- host orchestration -----------------------------------------
extern "C" void kernel_launch(void* const* d_in, const int* in_sizes, int n_in,
                              void* d_out, int out_size) {
    const int*   seed_index = (const int*)  d_in[0];
    const float* es_in      = (const float*)d_in[1];
    const float* ps_in      = (const float*)d_in[2];
    const int*   erows      = (const int*)  d_in[3];
    const int*   ecols      = (const int*)  d_in[4];
    const float* evals      = (const float*)d_in[5];
    const float* prm[16];
    for (int i = 0; i < 16; i++) prm[i] = (const float*)d_in[6 + i];
    const float* fc_w = (const float*)d_in[22];
    const float* fc_b = (const float*)d_in[23];

    float* out        = (float*)d_out;
    float* out_logits = out;
    float* out_es     = out + (size_t)E_N * C_N;
    float* out_ps     = out_es + (size_t)E_N * D_N;

    float *p_es, *p_ps, *p_msg, *p_g1, *p_g2;
    cudaGetSymbolAddress((void**)&p_es,  g_es);
    cudaGetSymbolAddress((void**)&p_ps,  g_ps);
    cudaGetSymbolAddress((void**)&p_msg, g_msg);
    cudaGetSymbolAddress((void**)&p_g1,  g_g1);
    cudaGetSymbolAddress((void**)&p_g2,  g_g2);

    cudaFuncSetAttribute(gemm_tf32_kernel,
                         cudaFuncAttributeMaxDynamicSharedMemorySize, GEMM_SMEM);

    const int scat_blocks = (NNZ_N * 32 + 255) / 256;
    const int p_rows = (P_N + TBM - 1) / TBM;
    const int e_rows = (E_N + TBM - 1) / TBM;

    for (int l = 0; l < 2; l++) {
        const float* eW[4] = {prm[l*8+0], prm[l*8+1], prm[l*8+2], prm[l*8+3]};
        const float* pW[4] = {prm[l*8+4], prm[l*8+5], prm[l*8+6], prm[l*8+7]};
        const float* es_src = (l == 0) ? es_in : p_es;
        const float* ps_src = (l == 0) ? ps_in : p_ps;
        float* es_dst = (l == 0) ? p_es : out_es;
        float* ps_dst = (l == 0) ? p_ps : out_ps;

        // seed mean of es at layer start
        seedmean_kernel<<<1, 128>>>(seed_index, es_src);

        // p_msg = segment_sum(es[edge_rows] * w, edge_cols)
        {
            int n4 = P_N * 32;
            zero_kernel<<<(n4 + 255) / 256, 256>>>(p_msg, n4);
        }
        scatter_kernel<<<scat_blocks, 256>>>(es_src, erows, ecols, evals, p_msg);

        // ps = GRU(p_msg, ps)
        gemm_tf32_kernel<<<dim3(6, p_rows), 256, GEMM_SMEM>>>(p_msg,  pW[0], pW[2], p_g1, P_N);
        gemm_tf32_kernel<<<dim3(6, p_rows), 256, GEMM_SMEM>>>(ps_src, pW[1], pW[3], p_g2, P_N);
        gate_kernel<<<(P_N * 32 + 255) / 256, 256>>>(p_g1, p_g2, ps_src, ps_dst, P_N);

        // e_msg = seed_mean + segment_sum(ps_new[edge_cols] * w, edge_rows)
        {
            int n4 = E_N * 32;
            bcast_mean_kernel<<<(n4 + 255) / 256, 256>>>(p_msg, n4);
        }
        scatter_kernel<<<scat_blocks, 256>>>(ps_dst, ecols, erows, evals, p_msg);

        // es = GRU(e_msg, es)
        gemm_tf32_kernel<<<dim3(6, e_rows), 256, GEMM_SMEM>>>(p_msg,  eW[0], eW[2], p_g1, E_N);
        gemm_tf32_kernel<<<dim3(6, e_rows), 256, GEMM_SMEM>>>(es_src, eW[1], eW[3], p_g2, E_N);
        gate_kernel<<<(E_N * 32 + 255) / 256, 256>>>(p_g1, p_g2, es_src, es_dst, E_N);
    }

    // logits = es @ fc_w^T + fc_b
    logits_kernel<<<(E_N + 7) / 8, 256>>>(out_es, fc_w, fc_b, out_logits);

    (void)in_sizes; (void)n_in; (void)out_size;
}